// round 1
// baseline (speedup 1.0000x reference)
#include <cuda_runtime.h>
#include <cmath>

static constexpr int H = 512, W = 512, BATCH = 8;
static constexpr int NPIX = H * W;
static constexpr int NXi = BATCH * 3 * NPIX;          // 6,291,456
static constexpr int NFEAT = BATCH * 32 * NPIX;       // 67,108,864
static constexpr int MAXB = 11;                       // max possible int(b) is 10
static constexpr int RBLOCKS = 512;

// Scratch feature maps (device globals per harness allocation rules)
__device__ float g_x1[NFEAT];
__device__ float g_x2[NFEAT];
__device__ float g_x3[NFEAT];
__device__ float g_part[RBLOCKS];
__device__ float g_sum[MAXB + 1];
__device__ float g_n3;
__device__ int   g_b;

// ---------------------------------------------------------------------------
// Deterministic 2-stage mean reduction. it = -1 -> unconditional (initial x).
// ---------------------------------------------------------------------------
__global__ void reduce1_k(const float* __restrict__ x, int it) {
    if (it >= 0 && it >= g_b) return;
    const float4* x4 = reinterpret_cast<const float4*>(x);
    const int n4 = NXi / 4;
    float s = 0.f;
    for (int i = blockIdx.x * 256 + threadIdx.x; i < n4; i += gridDim.x * 256) {
        float4 v = x4[i];
        s += (v.x + v.y) + (v.z + v.w);
    }
#pragma unroll
    for (int o = 16; o; o >>= 1) s += __shfl_xor_sync(0xffffffffu, s, o);
    __shared__ float ws[8];
    if ((threadIdx.x & 31) == 0) ws[threadIdx.x >> 5] = s;
    __syncthreads();
    if (threadIdx.x < 32) {
        s = (threadIdx.x < 8) ? ws[threadIdx.x] : 0.f;
#pragma unroll
        for (int o = 4; o; o >>= 1) s += __shfl_xor_sync(0xffffffffu, s, o);
        if (threadIdx.x == 0) g_part[blockIdx.x] = s;
    }
}

__global__ void reduce2_k(int slot, int it) {
    if (it >= 0 && it >= g_b) return;
    float s = 0.f;
    for (int i = threadIdx.x; i < RBLOCKS; i += 256) s += g_part[i];
#pragma unroll
    for (int o = 16; o; o >>= 1) s += __shfl_xor_sync(0xffffffffu, s, o);
    __shared__ float ws[8];
    if ((threadIdx.x & 31) == 0) ws[threadIdx.x >> 5] = s;
    __syncthreads();
    if (threadIdx.x == 0) {
        float t = 0.f;
#pragma unroll
        for (int i = 0; i < 8; i++) t += ws[i];
        g_sum[slot] = t;
    }
}

// Compute n3 and loop count b from mean of the original input (f64 math,
// matching the python-float host computation in the reference).
__global__ void params_k() {
    float m32 = g_sum[0] / (float)NXi;
    double xx1 = (double)m32;
    double s = xx1 * xx1;
    double n3 = -0.79 * s + 0.81 * xx1 + 1.4;
    double bf;
    if (xx1 < 0.1)       bf = -25.0 * xx1 + 10.0;
    else if (xx1 < 0.45) bf = 17.14 * s - 15.14 * xx1 + 10.0;
    else                 bf = 5.66 * s - 2.93 * xx1 + 7.2;
    g_n3 = (float)n3;
    int b = (int)bf;
    if (b > MAXB) b = MAXB;
    g_b = b;
}

// ---------------------------------------------------------------------------
// Direct 3x3 conv, stride 1, SAME (zero pad), ReLU. COUT = 32.
// Block: 256 threads; pixel tile 32x8; each thread: 4 consecutive-x pixels
// for 8 output channels (thread group tg = t/64 picks cout slice).
// transform != 0 -> input is (1 - v) (conv1 on the 1-x branch).
// ---------------------------------------------------------------------------
template <int CIN>
__global__ void __launch_bounds__(256) conv3x3_k(
    const float* __restrict__ in, const float* __restrict__ wg,
    const float* __restrict__ bg, float* __restrict__ out, int transform)
{
    __shared__ float w_s[CIN * 9 * 32];
    __shared__ float tile[10 * 35];   // rows 10 (8+halo), stride 35 -> conflict-free
    const int t  = threadIdx.x;
    const int tg = t >> 6;            // cout group 0..3
    const int pt = t & 63;
    const int lx = (pt & 7) << 2;     // 0..28
    const int ly = pt >> 3;           // 0..7
    const int bx = blockIdx.x << 5;
    const int by = blockIdx.y << 3;
    const int bb = blockIdx.z;

    for (int i = t; i < CIN * 9 * 32; i += 256) {
        int cout = i & 31;
        int rem  = i >> 5;            // cin*9 + tap
        int cin  = rem / 9, tap = rem - cin * 9;
        w_s[i] = wg[(cout * CIN + cin) * 9 + tap];
    }

    float acc[8][4];
#pragma unroll
    for (int c = 0; c < 8; c++)
#pragma unroll
        for (int p = 0; p < 4; p++) acc[c][p] = 0.f;

    const float* inb = in + (long long)bb * CIN * NPIX;

    for (int cin = 0; cin < CIN; ++cin) {
        __syncthreads();
        const float* ip = inb + (long long)cin * NPIX;
        for (int i = t; i < 340; i += 256) {      // 10 rows x 34 cols
            int r = i / 34, c = i - r * 34;
            int gy = by - 1 + r, gx = bx - 1 + c;
            float v = 0.f;
            if ((unsigned)gy < (unsigned)H && (unsigned)gx < (unsigned)W) {
                v = ip[gy * W + gx];
                if (transform) v = 1.0f - v;
            }
            tile[r * 35 + c] = v;
        }
        __syncthreads();
        const float* wb = &w_s[cin * 288 + tg * 8];
#pragma unroll
        for (int ky = 0; ky < 3; ++ky) {
            float iv[6];
#pragma unroll
            for (int j = 0; j < 6; ++j) iv[j] = tile[(ly + ky) * 35 + lx + j];
#pragma unroll
            for (int kx = 0; kx < 3; ++kx) {
                const float* wv = wb + (ky * 3 + kx) * 32;
#pragma unroll
                for (int c = 0; c < 8; ++c) {
                    float wf = wv[c];
#pragma unroll
                    for (int p = 0; p < 4; ++p)
                        acc[c][p] = fmaf(iv[kx + p], wf, acc[c][p]);
                }
            }
        }
    }

    const int oy = by + ly, ox = bx + lx;
#pragma unroll
    for (int c = 0; c < 8; ++c) {
        int cout = tg * 8 + c;
        float bv = bg[cout];
        float4 o;
        o.x = fmaxf(acc[c][0] + bv, 0.f);
        o.y = fmaxf(acc[c][1] + bv, 0.f);
        o.z = fmaxf(acc[c][2] + bv, 0.f);
        o.w = fmaxf(acc[c][3] + bv, 0.f);
        *reinterpret_cast<float4*>(
            &out[((long long)(bb * 32 + cout)) * NPIX + oy * W + ox]) = o;
    }
}

// ---------------------------------------------------------------------------
// conv7: cin=64 (concat of x1 and x3), cout=3, tanh, scaled 0.5,
// accumulate=0 -> write, accumulate=1 -> add (averaging the two branches).
// Pixel tile 32x32; each thread: 4 x-pixels, all 3 couts.
// ---------------------------------------------------------------------------
__global__ void __launch_bounds__(256) conv7_k(
    const float* __restrict__ x1, const float* __restrict__ x3,
    const float* __restrict__ wg, const float* __restrict__ bg,
    float* __restrict__ out, int accumulate)
{
    __shared__ float w_s[64 * 9 * 3];
    __shared__ float tile[34 * 35];
    const int t  = threadIdx.x;
    const int lx = (t & 7) << 2;
    const int ly = t >> 3;            // 0..31
    const int bx = blockIdx.x << 5;
    const int by = blockIdx.y << 5;
    const int bb = blockIdx.z;

    for (int i = t; i < 64 * 9 * 3; i += 256) {
        int cout = i % 3;
        int rem  = i / 3;
        int cin  = rem / 9, tap = rem - cin * 9;
        w_s[i] = wg[(cout * 64 + cin) * 9 + tap];
    }

    float acc[3][4];
#pragma unroll
    for (int c = 0; c < 3; c++)
#pragma unroll
        for (int p = 0; p < 4; p++) acc[c][p] = 0.f;

    for (int cin = 0; cin < 64; ++cin) {
        const float* ip = (cin < 32)
            ? x1 + ((long long)(bb * 32 + cin)) * NPIX
            : x3 + ((long long)(bb * 32 + cin - 32)) * NPIX;
        __syncthreads();
        for (int i = t; i < 34 * 34; i += 256) {
            int r = i / 34, c = i - r * 34;
            int gy = by - 1 + r, gx = bx - 1 + c;
            tile[r * 35 + c] =
                ((unsigned)gy < (unsigned)H && (unsigned)gx < (unsigned)W)
                    ? ip[gy * W + gx] : 0.f;
        }
        __syncthreads();
        const float* wb = &w_s[cin * 27];
#pragma unroll
        for (int ky = 0; ky < 3; ++ky) {
            float iv[6];
#pragma unroll
            for (int j = 0; j < 6; ++j) iv[j] = tile[(ly + ky) * 35 + lx + j];
#pragma unroll
            for (int kx = 0; kx < 3; ++kx) {
                const float* wv = wb + (ky * 3 + kx) * 3;
#pragma unroll
                for (int c = 0; c < 3; ++c) {
                    float wf = wv[c];
#pragma unroll
                    for (int p = 0; p < 4; ++p)
                        acc[c][p] = fmaf(iv[kx + p], wf, acc[c][p]);
                }
            }
        }
    }

    const int oy = by + ly, ox = bx + lx;
#pragma unroll
    for (int c = 0; c < 3; ++c) {
        float bv = bg[c];
        float4 o;
        o.x = 0.5f * tanhf(acc[c][0] + bv);
        o.y = 0.5f * tanhf(acc[c][1] + bv);
        o.z = 0.5f * tanhf(acc[c][2] + bv);
        o.w = 0.5f * tanhf(acc[c][3] + bv);
        float4* op = reinterpret_cast<float4*>(
            &out[((long long)(bb * 3 + c)) * NPIX + oy * W + ox]);
        if (accumulate) {
            float4 prev = *op;
            o.x += prev.x; o.y += prev.y; o.z += prev.z; o.w += prev.w;
        }
        *op = o;
    }
}

// ---------------------------------------------------------------------------
__global__ void copy_k(float* __restrict__ dst, const float* __restrict__ src) {
    int i = blockIdx.x * 256 + threadIdx.x;
    if (i < NXi / 4)
        reinterpret_cast<float4*>(dst)[i] =
            reinterpret_cast<const float4*>(src)[i];
}

// x = x + x_r * (x*x - x) * ((0.63 - m) / (n3 - m)); no-op when it >= b.
__global__ void update_k(float* __restrict__ x, const float* __restrict__ xr, int it) {
    if (it >= g_b) return;
    float m  = g_sum[it + 1] / (float)NXi;
    float cf = (0.63f - m) / (g_n3 - m);
    int i = blockIdx.x * 256 + threadIdx.x;
    if (i >= NXi / 4) return;
    float4 xv = reinterpret_cast<float4*>(x)[i];
    float4 rv = reinterpret_cast<const float4*>(xr)[i];
    xv.x += rv.x * (xv.x * xv.x - xv.x) * cf;
    xv.y += rv.y * (xv.y * xv.y - xv.y) * cf;
    xv.z += rv.z * (xv.z * xv.z - xv.z) * cf;
    xv.w += rv.w * (xv.w * xv.w - xv.w) * cf;
    reinterpret_cast<float4*>(x)[i] = xv;
}

// ---------------------------------------------------------------------------
extern "C" void kernel_launch(void* const* d_in, const int* in_sizes, int n_in,
                              void* d_out, int out_size)
{
    const float* x  = (const float*)d_in[0];
    const float* w1 = (const float*)d_in[1];
    const float* b1 = (const float*)d_in[2];
    const float* w2 = (const float*)d_in[3];
    const float* b2 = (const float*)d_in[4];
    const float* w3 = (const float*)d_in[5];
    const float* b3 = (const float*)d_in[6];
    const float* w7 = (const float*)d_in[7];
    const float* b7 = (const float*)d_in[8];

    float* xo = (float*)d_out;      // final x
    float* xr = xo + NXi;           // x_r

    float *px1, *px2, *px3;
    cudaGetSymbolAddress((void**)&px1, g_x1);
    cudaGetSymbolAddress((void**)&px2, g_x2);
    cudaGetSymbolAddress((void**)&px3, g_x3);

    dim3 blk(256);
    dim3 cg(16, 64, 8);      // 32x8 tiles over 512x512, batch 8
    dim3 c7g(16, 16, 8);     // 32x32 tiles
    int eg = (NXi / 4 + 255) / 256;

    // b / n3 from mean of original x
    reduce1_k<<<RBLOCKS, blk>>>(x, -1);
    reduce2_k<<<1, blk>>>(0, -1);
    params_k<<<1, 1>>>();

    // Two CNN branches (x and 1-x), shared weights, averaged output
    for (int br = 0; br < 2; ++br) {
        conv3x3_k<3><<<cg, blk>>>(x, w1, b1, px1, br);
        conv3x3_k<32><<<cg, blk>>>(px1, w2, b2, px2, 0);
        conv3x3_k<32><<<cg, blk>>>(px2, w3, b3, px3, 0);
        conv7_k<<<c7g, blk>>>(px1, px3, w7, b7, xr, br);
    }

    // Iterative mean-feedback refinement (fixed launch count, device-guarded)
    copy_k<<<eg, blk>>>(xo, x);
    for (int it = 0; it < MAXB; ++it) {
        reduce1_k<<<RBLOCKS, blk>>>(xo, it);
        reduce2_k<<<1, blk>>>(it + 1, it);
        update_k<<<eg, blk>>>(xo, xr, it);
    }
}